// round 1
// baseline (speedup 1.0000x reference)
#include <cuda_runtime.h>

#define N 8192
#define IN_F 512
#define OUT_F 64
#define NEG_SLOPE 0.01f
#define MASK_VAL -1e9f

// Scratch (allocation-free rule: device globals)
__device__ __align__(16) float g_WH[N * OUT_F];
__device__ float g_wh1[N];
__device__ float g_wh2[N];

// ---------------------------------------------------------------------------
// Kernel A: WH = h @ W   [8192,512] @ [512,64]
// 256 blocks x 256 threads, 32 rows per block, K chunked by 64.
// ---------------------------------------------------------------------------
__global__ void __launch_bounds__(256) wh_kernel(const float* __restrict__ h,
                                                 const float* __restrict__ W) {
    __shared__ float Wc[64 * OUT_F];   // 16 KB
    __shared__ float hc[32 * 64];      // 8 KB

    const int t  = threadIdx.x;
    const int f  = t & 63;
    const int rg = t >> 6;             // 0..3
    const int r0 = blockIdx.x * 32;

    float acc[8];
#pragma unroll
    for (int i = 0; i < 8; i++) acc[i] = 0.f;

    for (int kc = 0; kc < IN_F; kc += 64) {
        __syncthreads();
#pragma unroll
        for (int i = 0; i < 16; i++) {
            int idx = t + i * 256;     // 4096 elems of W chunk
            Wc[idx] = W[(size_t)(kc + (idx >> 6)) * OUT_F + (idx & 63)];
        }
#pragma unroll
        for (int i = 0; i < 8; i++) {
            int idx = t + i * 256;     // 2048 elems of h chunk
            hc[idx] = h[(size_t)(r0 + (idx >> 6)) * IN_F + kc + (idx & 63)];
        }
        __syncthreads();
#pragma unroll 8
        for (int k = 0; k < 64; k++) {
            float w = Wc[k * 64 + f];
#pragma unroll
            for (int i = 0; i < 8; i++)
                acc[i] += hc[(rg * 8 + i) * 64 + k] * w;
        }
    }
#pragma unroll
    for (int i = 0; i < 8; i++)
        g_WH[(size_t)(r0 + rg * 8 + i) * OUT_F + f] = acc[i];
}

// ---------------------------------------------------------------------------
// Kernel B: wh1[r] = WH[r,:] . a[:64],  wh2[r] = WH[r,:] . a[64:]
// one warp per row, warp shuffle reduction
// ---------------------------------------------------------------------------
__global__ void __launch_bounds__(256) attn_vec_kernel(const float* __restrict__ a) {
    const int warp = threadIdx.x >> 5;
    const int lane = threadIdx.x & 31;
    const int r = blockIdx.x * 8 + warp;

    float2 v = ((const float2*)(g_WH + (size_t)r * OUT_F))[lane];
    float d1 = v.x * a[2 * lane] + v.y * a[2 * lane + 1];
    float d2 = v.x * a[OUT_F + 2 * lane] + v.y * a[OUT_F + 2 * lane + 1];
#pragma unroll
    for (int off = 16; off > 0; off >>= 1) {
        d1 += __shfl_xor_sync(0xFFFFFFFFu, d1, off);
        d2 += __shfl_xor_sync(0xFFFFFFFFu, d2, off);
    }
    if (lane == 0) {
        g_wh1[r] = d1;
        g_wh2[r] = d2;
    }
}

// ---------------------------------------------------------------------------
// Kernel C: fused masked-softmax attention + PV matmul + elu
// 128 blocks (64 rows each) x 256 threads; j streamed in tiles of 64.
// Online softmax with m initialized to MASK_VAL (matches reference semantics
// even for fully-masked prefixes).
// Thread tile: 4 rows x 4 features (tx = feature group, ty = row group).
// ---------------------------------------------------------------------------
#define TI 64
#define TJ 64
#define PSTR 66   // Ps row stride (even -> aligned float2, %32==2 -> low conflicts)

__global__ void __launch_bounds__(256) gat_kernel(const int* __restrict__ adj,
                                                  float* __restrict__ out) {
    __shared__ __align__(16) float WHs[TJ * OUT_F];   // 16 KB  V tile
    __shared__ __align__(16) float Ps[TI * PSTR];     // ~16.5 KB scores/probs
    __shared__ float wh1s[TI];
    __shared__ float wh2s[TJ];
    __shared__ float m_s[TI], s_s[TI], scale_s[TI];
    __shared__ float red[4 * TI];

    const int t  = threadIdx.x;
    const int tx = t & 15;      // features tx*4 .. tx*4+3
    const int ty = t >> 4;      // rows    ty*4 .. ty*4+3
    const int i0 = blockIdx.x * TI;
    const int r_lane = t & 63;  // mapping for max/exp phases
    const int lane4  = t >> 6;

    if (t < TI) {
        wh1s[t] = g_wh1[i0 + t];
        m_s[t]  = MASK_VAL;
        s_s[t]  = 0.f;
    }

    float acc[4][4];
#pragma unroll
    for (int i = 0; i < 4; i++)
#pragma unroll
        for (int c = 0; c < 4; c++) acc[i][c] = 0.f;

    for (int j0 = 0; j0 < N; j0 += TJ) {
        __syncthreads();   // previous matmul done; safe to overwrite WHs/Ps

        // ---- load V tile (64x64 floats = 1024 float4) + wh2 slice ----
#pragma unroll
        for (int i = 0; i < 4; i++) {
            int idx = t + i * 256;
            ((float4*)WHs)[idx] = ((const float4*)g_WH)[(size_t)j0 * (OUT_F / 4) + idx];
        }
        if (t < TJ) wh2s[t] = g_wh2[j0 + t];
        __syncthreads();

        // ---- masked leaky-relu scores into Ps (int4 adjacency loads) ----
#pragma unroll
        for (int k = 0; k < 4; k++) {
            int idx = t + k * 256;           // 1024 int4 entries in tile
            int r  = idx >> 4;
            int jb = (idx & 15) << 2;
            int4 av = *(const int4*)(adj + (size_t)(i0 + r) * N + j0 + jb);
            float b = wh1s[r];
            float e0 = b + wh2s[jb + 0]; e0 = (e0 > 0.f) ? e0 : NEG_SLOPE * e0;
            float e1 = b + wh2s[jb + 1]; e1 = (e1 > 0.f) ? e1 : NEG_SLOPE * e1;
            float e2 = b + wh2s[jb + 2]; e2 = (e2 > 0.f) ? e2 : NEG_SLOPE * e2;
            float e3 = b + wh2s[jb + 3]; e3 = (e3 > 0.f) ? e3 : NEG_SLOPE * e3;
            float* pr = &Ps[r * PSTR + jb];
            pr[0] = (av.x > 0) ? e0 : MASK_VAL;
            pr[1] = (av.y > 0) ? e1 : MASK_VAL;
            pr[2] = (av.z > 0) ? e2 : MASK_VAL;
            pr[3] = (av.w > 0) ? e3 : MASK_VAL;
        }
        __syncthreads();

        // ---- per-row tile max (4 partials per row) ----
        {
            float mx = MASK_VAL;
            const float* pr = &Ps[r_lane * PSTR + lane4];
#pragma unroll
            for (int jj = 0; jj < 16; jj++) mx = fmaxf(mx, pr[jj * 4]);
            red[lane4 * TI + r_lane] = mx;
        }
        __syncthreads();
        if (t < TI) {
            float mx = fmaxf(fmaxf(red[t], red[TI + t]),
                             fmaxf(red[2 * TI + t], red[3 * TI + t]));
            float mo = m_s[t];
            float mn = fmaxf(mo, mx);
            scale_s[t] = __expf(mo - mn);   // 0 on first real tile, 1 if unchanged
            m_s[t] = mn;
        }
        __syncthreads();

        // ---- exp in place + per-row partial sums ----
        {
            float m  = m_s[r_lane];
            float sm = 0.f;
            float* pr = &Ps[r_lane * PSTR + lane4];
#pragma unroll
            for (int jj = 0; jj < 16; jj++) {
                float p = __expf(pr[jj * 4] - m);   // masked -> exp(-1e9) = 0
                pr[jj * 4] = p;
                sm += p;
            }
            red[lane4 * TI + r_lane] = sm;
        }
        __syncthreads();
        if (t < TI)
            s_s[t] = s_s[t] * scale_s[t]
                   + red[t] + red[TI + t] + red[2 * TI + t] + red[3 * TI + t];
        // (matmul below reads Ps/scale_s/WHs only -> no hazard with s_s update)

        // ---- rescale accumulators, then P-tile @ V-tile ----
#pragma unroll
        for (int i = 0; i < 4; i++) {
            float sc = scale_s[ty * 4 + i];
#pragma unroll
            for (int c = 0; c < 4; c++) acc[i][c] *= sc;
        }
#pragma unroll 4
        for (int j = 0; j < TJ; j += 2) {
            float4 w0 = ((const float4*)WHs)[(j + 0) * (OUT_F / 4) + tx];
            float4 w1 = ((const float4*)WHs)[(j + 1) * (OUT_F / 4) + tx];
#pragma unroll
            for (int i = 0; i < 4; i++) {
                float2 p = *(const float2*)&Ps[(ty * 4 + i) * PSTR + j];
                acc[i][0] += p.x * w0.x; acc[i][1] += p.x * w0.y;
                acc[i][2] += p.x * w0.z; acc[i][3] += p.x * w0.w;
                acc[i][0] += p.y * w1.x; acc[i][1] += p.y * w1.y;
                acc[i][2] += p.y * w1.z; acc[i][3] += p.y * w1.w;
            }
        }
    }

    __syncthreads();   // final s_s visible to all
#pragma unroll
    for (int i = 0; i < 4; i++) {
        int r = ty * 4 + i;
        float inv = 1.f / s_s[r];
        float4 o;
        float v;
        v = acc[i][0] * inv; o.x = (v > 0.f) ? v : expm1f(v);
        v = acc[i][1] * inv; o.y = (v > 0.f) ? v : expm1f(v);
        v = acc[i][2] * inv; o.z = (v > 0.f) ? v : expm1f(v);
        v = acc[i][3] * inv; o.w = (v > 0.f) ? v : expm1f(v);
        ((float4*)out)[(size_t)(i0 + r) * (OUT_F / 4) + tx] = o;
    }
}

// ---------------------------------------------------------------------------
extern "C" void kernel_launch(void* const* d_in, const int* in_sizes, int n_in,
                              void* d_out, int out_size) {
    const float* h   = nullptr;
    const int*   adj = nullptr;
    const float* W   = nullptr;
    const float* a   = nullptr;
    for (int i = 0; i < n_in; i++) {
        long long sz = in_sizes[i];
        if (sz == (long long)N * IN_F)        h   = (const float*)d_in[i];
        else if (sz == (long long)N * N)      adj = (const int*)d_in[i];
        else if (sz == (long long)IN_F * OUT_F) W = (const float*)d_in[i];
        else if (sz == 2 * OUT_F)             a   = (const float*)d_in[i];
    }

    wh_kernel<<<N / 32, 256>>>(h, W);
    attn_vec_kernel<<<N / 8, 256>>>(a);
    gat_kernel<<<N / TI, 256>>>(adj, (float*)d_out);
}

// round 3
// speedup vs baseline: 1.4356x; 1.4356x over previous
#include <cuda_runtime.h>
#include <cstdint>

#define N 8192
#define IN_F 512
#define OUT_F 64
#define NEG_SLOPE 0.01f
#define MASK_VAL -1e9f

// Scratch (allocation-free rule: device globals)
__device__ __align__(16) float g_WH[N * OUT_F];
__device__ float g_wh1[N];
__device__ float g_wh2[N];
__device__ float g_M;

__device__ __forceinline__ uint32_t su(const void* p) {
    return (uint32_t)__cvta_generic_to_shared(p);
}
#define CP_ASYNC16(dst, src) \
    asm volatile("cp.async.cg.shared.global [%0], [%1], 16;" :: "r"(dst), "l"(src))
#define CP_COMMIT() asm volatile("cp.async.commit_group;" ::: "memory")
#define CP_WAIT0()  asm volatile("cp.async.wait_group 0;" ::: "memory")

// ---------------------------------------------------------------------------
// Kernel A: WH = h @ W   [8192,512] @ [512,64]
// 512 blocks x 256 threads, 16 rows per block, K chunked by 128.
// ---------------------------------------------------------------------------
__global__ void __launch_bounds__(256) wh_kernel(const float* __restrict__ h,
                                                 const float* __restrict__ W) {
    __shared__ __align__(16) float Wc[128 * OUT_F];  // 32 KB
    __shared__ __align__(16) float hc[16 * 128];     // 8 KB

    const int t  = threadIdx.x;
    const int f  = t & 63;
    const int rg = t >> 6;              // 0..3 -> rows rg*4 .. rg*4+3
    const int r0 = blockIdx.x * 16;

    float acc[4] = {0.f, 0.f, 0.f, 0.f};

    for (int kc = 0; kc < IN_F; kc += 128) {
        __syncthreads();
#pragma unroll
        for (int i = 0; i < 8; i++) {           // 2048 float4 of W chunk
            int idx = t + i * 256;
            ((float4*)Wc)[idx] = ((const float4*)W)[(size_t)(kc + (idx >> 4)) * 16 + (idx & 15)];
        }
#pragma unroll
        for (int i = 0; i < 2; i++) {           // 512 float4 of h chunk
            int idx = t + i * 256;
            ((float4*)hc)[idx] =
                ((const float4*)h)[(size_t)(r0 + (idx >> 5)) * (IN_F / 4) + (kc >> 2) + (idx & 31)];
        }
        __syncthreads();
#pragma unroll 8
        for (int k = 0; k < 128; k++) {
            float w = Wc[k * 64 + f];
#pragma unroll
            for (int i = 0; i < 4; i++)
                acc[i] += hc[(rg * 4 + i) * 128 + k] * w;
        }
    }
#pragma unroll
    for (int i = 0; i < 4; i++)
        g_WH[(size_t)(r0 + rg * 4 + i) * OUT_F + f] = acc[i];
}

// ---------------------------------------------------------------------------
// Kernel B: wh1/wh2 row dots, one warp per row
// ---------------------------------------------------------------------------
__global__ void __launch_bounds__(256) attn_vec_kernel(const float* __restrict__ a) {
    const int warp = threadIdx.x >> 5;
    const int lane = threadIdx.x & 31;
    const int r = blockIdx.x * 8 + warp;

    float2 v = ((const float2*)(g_WH + (size_t)r * OUT_F))[lane];
    float d1 = v.x * a[2 * lane] + v.y * a[2 * lane + 1];
    float d2 = v.x * a[OUT_F + 2 * lane] + v.y * a[OUT_F + 2 * lane + 1];
#pragma unroll
    for (int off = 16; off > 0; off >>= 1) {
        d1 += __shfl_xor_sync(0xFFFFFFFFu, d1, off);
        d2 += __shfl_xor_sync(0xFFFFFFFFu, d2, off);
    }
    if (lane == 0) {
        g_wh1[r] = d1;
        g_wh2[r] = d2;
    }
}

// ---------------------------------------------------------------------------
// Kernel B2: global softmax shift M = max(wh1) + max(wh2)
// ---------------------------------------------------------------------------
__global__ void __launch_bounds__(256) max_kernel() {
    __shared__ float s1[256], s2[256];
    const int t = threadIdx.x;
    float m1 = -1e30f, m2 = -1e30f;
    for (int i = t; i < N; i += 256) {
        m1 = fmaxf(m1, g_wh1[i]);
        m2 = fmaxf(m2, g_wh2[i]);
    }
    s1[t] = m1; s2[t] = m2;
    __syncthreads();
    for (int s = 128; s > 0; s >>= 1) {
        if (t < s) {
            s1[t] = fmaxf(s1[t], s1[t + s]);
            s2[t] = fmaxf(s2[t], s2[t + s]);
        }
        __syncthreads();
    }
    if (t == 0) g_M = s1[0] + s2[0];
}

// ---------------------------------------------------------------------------
// Kernel C: fused masked attention + PV matmul + elu
//  - fixed global shift M (no online softmax, row sums in registers)
//  - packed fma.rn.f32x2 matmul (2x FLOP rate)
//  - cp.async double-buffered V tiles, register-prefetched adjacency
// ---------------------------------------------------------------------------
#define TI 64
#define TJ 64
#define PSTR 68   // multiple of 4 (float4-aligned rows); 68 % 32 = 4
#define NT (N / TJ)

__global__ void __launch_bounds__(256) gat_kernel(const int* __restrict__ adj,
                                                  float* __restrict__ out) {
    __shared__ __align__(16) float VB[2 * TJ * OUT_F];  // 32 KB double-buffered V
    __shared__ __align__(16) float Ps[TI * PSTR];       // 17 KB
    __shared__ __align__(16) float wh2s[2][TJ];
    __shared__ float wh1s[TI];
    __shared__ float red[TI * 16];
    __shared__ float s_s[TI];

    const int t   = threadIdx.x;
    const int tx  = t & 15;            // matmul: feature group tx*4..tx*4+3
    const int ty  = t >> 4;            // matmul: rows ty*4..ty*4+3
    const int rsc = t >> 4;            // score rows: rsc + 16k
    const int jb  = (t & 15) * 4;      // score cols within tile
    const int i0  = blockIdx.x * TI;

    if (t < TI) wh1s[t] = g_wh1[i0 + t];
    const float Mv = g_M;

    // -- prologue: prefetch tile 0 (V + wh2 via cp.async, adjacency in regs) --
#pragma unroll
    for (int i = 0; i < 4; i++) {
        int idx = t + i * 256;
        CP_ASYNC16(su(&VB[idx * 4]), (const void*)&g_WH[idx * 4]);
    }
    if (t < 16) CP_ASYNC16(su(&wh2s[0][t * 4]), (const void*)&g_wh2[t * 4]);
    CP_COMMIT();

    int4 a4[4];
#pragma unroll
    for (int k = 0; k < 4; k++)
        a4[k] = *(const int4*)(adj + (size_t)(i0 + rsc + 16 * k) * N + jb);

    float sums[4] = {0.f, 0.f, 0.f, 0.f};
    unsigned long long acc[4][2];
#pragma unroll
    for (int i = 0; i < 4; i++) { acc[i][0] = 0ull; acc[i][1] = 0ull; }

    for (int it = 0; it < NT; ++it) {
        const int b = it & 1;
        CP_WAIT0();
        __syncthreads();   // V[it] visible; prev matmul done (Ps reusable)

        // ---- scores + exp + register row-sums ----
#pragma unroll
        for (int k = 0; k < 4; k++) {
            const int r = rsc + 16 * k;
            const float b1 = wh1s[r];
            const float4 w2 = *(const float4*)&wh2s[b][jb];
            float e0 = b1 + w2.x; e0 = (e0 > 0.f) ? e0 : NEG_SLOPE * e0;
            float e1 = b1 + w2.y; e1 = (e1 > 0.f) ? e1 : NEG_SLOPE * e1;
            float e2 = b1 + w2.z; e2 = (e2 > 0.f) ? e2 : NEG_SLOPE * e2;
            float e3 = b1 + w2.w; e3 = (e3 > 0.f) ? e3 : NEG_SLOPE * e3;
            float p0 = (a4[k].x > 0) ? __expf(e0 - Mv) : 0.f;
            float p1 = (a4[k].y > 0) ? __expf(e1 - Mv) : 0.f;
            float p2 = (a4[k].z > 0) ? __expf(e2 - Mv) : 0.f;
            float p3 = (a4[k].w > 0) ? __expf(e3 - Mv) : 0.f;
            sums[k] += (p0 + p1) + (p2 + p3);
            *(float4*)&Ps[r * PSTR + jb] = make_float4(p0, p1, p2, p3);
        }

        // ---- prefetch next tile ----
        if (it + 1 < NT) {
            const int jn = (it + 1) * TJ;
#pragma unroll
            for (int k = 0; k < 4; k++)
                a4[k] = *(const int4*)(adj + (size_t)(i0 + rsc + 16 * k) * N + jn + jb);
            float* vb = VB + (b ^ 1) * (TJ * OUT_F);
#pragma unroll
            for (int i = 0; i < 4; i++) {
                int idx = t + i * 256;
                CP_ASYNC16(su(&vb[idx * 4]), (const void*)&g_WH[(size_t)jn * OUT_F + idx * 4]);
            }
            if (t < 16) CP_ASYNC16(su(&wh2s[b ^ 1][t * 4]), (const void*)&g_wh2[jn + t * 4]);
        }
        CP_COMMIT();
        __syncthreads();   // Ps visible

        // ---- matmul: acc += P-tile @ V-tile  (packed f32x2) ----
        const float* vb = VB + b * (TJ * OUT_F);
#pragma unroll 4
        for (int j = 0; j < TJ; j += 2) {
            ulonglong2 w0 = *(const ulonglong2*)&vb[(j + 0) * OUT_F + tx * 4];
            ulonglong2 w1 = *(const ulonglong2*)&vb[(j + 1) * OUT_F + tx * 4];
#pragma unroll
            for (int i = 0; i < 4; i++) {
                float2 p = *(const float2*)&Ps[(ty * 4 + i) * PSTR + j];
                unsigned long long pxx, pyy;
                asm("mov.b64 %0, {%1, %1};" : "=l"(pxx) : "f"(p.x));
                asm("fma.rn.f32x2 %0, %1, %2, %0;" : "+l"(acc[i][0]) : "l"(pxx), "l"(w0.x));
                asm("fma.rn.f32x2 %0, %1, %2, %0;" : "+l"(acc[i][1]) : "l"(pxx), "l"(w0.y));
                asm("mov.b64 %0, {%1, %1};" : "=l"(pyy) : "f"(p.y));
                asm("fma.rn.f32x2 %0, %1, %2, %0;" : "+l"(acc[i][0]) : "l"(pyy), "l"(w1.x));
                asm("fma.rn.f32x2 %0, %1, %2, %0;" : "+l"(acc[i][1]) : "l"(pyy), "l"(w1.y));
            }
        }
    }

    // ---- row-sum reduction (16 partials per row) ----
#pragma unroll
    for (int k = 0; k < 4; k++)
        red[(rsc + 16 * k) * 16 + tx] = sums[k];
    __syncthreads();
    if (t < TI) {
        float s = 0.f;
#pragma unroll
        for (int q = 0; q < 16; q++) s += red[t * 16 + q];
        s_s[t] = s;
    }
    __syncthreads();

    // ---- epilogue: normalize + elu + store ----
#pragma unroll
    for (int i = 0; i < 4; i++) {
        const int r = ty * 4 + i;
        const float inv = 1.f / s_s[r];
        float v0, v1, v2, v3;
        asm("mov.b64 {%0, %1}, %2;" : "=f"(v0), "=f"(v1) : "l"(acc[i][0]));
        asm("mov.b64 {%0, %1}, %2;" : "=f"(v2), "=f"(v3) : "l"(acc[i][1]));
        float4 o;
        float v;
        v = v0 * inv; o.x = (v > 0.f) ? v : expm1f(v);
        v = v1 * inv; o.y = (v > 0.f) ? v : expm1f(v);
        v = v2 * inv; o.z = (v > 0.f) ? v : expm1f(v);
        v = v3 * inv; o.w = (v > 0.f) ? v : expm1f(v);
        ((float4*)out)[(size_t)(i0 + r) * (OUT_F / 4) + tx] = o;
    }
}

// ---------------------------------------------------------------------------
extern "C" void kernel_launch(void* const* d_in, const int* in_sizes, int n_in,
                              void* d_out, int out_size) {
    const float* h   = nullptr;
    const int*   adj = nullptr;
    const float* W   = nullptr;
    const float* a   = nullptr;
    for (int i = 0; i < n_in; i++) {
        long long sz = in_sizes[i];
        if (sz == (long long)N * IN_F)          h   = (const float*)d_in[i];
        else if (sz == (long long)N * N)        adj = (const int*)d_in[i];
        else if (sz == (long long)IN_F * OUT_F) W   = (const float*)d_in[i];
        else if (sz == 2 * OUT_F)               a   = (const float*)d_in[i];
    }

    wh_kernel<<<N / 16, 256>>>(h, W);
    attn_vec_kernel<<<N / 8, 256>>>(a);
    max_kernel<<<1, 256>>>();
    gat_kernel<<<N / TI, 256>>>(adj, (float*)d_out);
}

// round 4
// speedup vs baseline: 1.8061x; 1.2581x over previous
#include <cuda_runtime.h>
#include <cstdint>

#define N 8192
#define IN_F 512
#define OUT_F 64
#define NEG_SLOPE 0.01f
#define MASK_VAL -1e9f

#define TI 64
#define TJ 64
#define PSTR 68      // multiple of 4 (float4-aligned rows); 68 % 32 = 4
#define SPLIT 4
#define JSPAN (N / SPLIT)      // 2048
#define NT_S (JSPAN / TJ)      // 32

// Scratch (allocation-free rule: device globals)
__device__ __align__(16) float g_WH[N * OUT_F];
__device__ float g_wh1[N];
__device__ float g_wh2[N];
__device__ float g_M;
__device__ __align__(16) float g_pacc[SPLIT * N * OUT_F];   // 8 MB partial PV
__device__ float g_psum[SPLIT * N];                         // partial row sums

__device__ __forceinline__ uint32_t su(const void* p) {
    return (uint32_t)__cvta_generic_to_shared(p);
}
#define CP_ASYNC16(dst, src) \
    asm volatile("cp.async.cg.shared.global [%0], [%1], 16;" :: "r"(dst), "l"(src))
#define CP_COMMIT() asm volatile("cp.async.commit_group;" ::: "memory")
#define CP_WAIT0()  asm volatile("cp.async.wait_group 0;" ::: "memory")

// ---------------------------------------------------------------------------
// Kernel A: WH = h @ W   [8192,512] @ [512,64]
// ---------------------------------------------------------------------------
__global__ void __launch_bounds__(256) wh_kernel(const float* __restrict__ h,
                                                 const float* __restrict__ W) {
    __shared__ __align__(16) float Wc[128 * OUT_F];  // 32 KB
    __shared__ __align__(16) float hc[16 * 128];     // 8 KB

    const int t  = threadIdx.x;
    const int f  = t & 63;
    const int rg = t >> 6;              // 0..3 -> rows rg*4 .. rg*4+3
    const int r0 = blockIdx.x * 16;

    float acc[4] = {0.f, 0.f, 0.f, 0.f};

    for (int kc = 0; kc < IN_F; kc += 128) {
        __syncthreads();
#pragma unroll
        for (int i = 0; i < 8; i++) {           // 2048 float4 of W chunk
            int idx = t + i * 256;
            ((float4*)Wc)[idx] = ((const float4*)W)[(size_t)(kc + (idx >> 4)) * 16 + (idx & 15)];
        }
#pragma unroll
        for (int i = 0; i < 2; i++) {           // 512 float4 of h chunk
            int idx = t + i * 256;
            ((float4*)hc)[idx] =
                ((const float4*)h)[(size_t)(r0 + (idx >> 5)) * (IN_F / 4) + (kc >> 2) + (idx & 31)];
        }
        __syncthreads();
#pragma unroll 8
        for (int k = 0; k < 128; k++) {
            float w = Wc[k * 64 + f];
#pragma unroll
            for (int i = 0; i < 4; i++)
                acc[i] += hc[(rg * 4 + i) * 128 + k] * w;
        }
    }
#pragma unroll
    for (int i = 0; i < 4; i++)
        g_WH[(size_t)(r0 + rg * 4 + i) * OUT_F + f] = acc[i];
}

// ---------------------------------------------------------------------------
// Kernel B: wh1/wh2 row dots, one warp per row
// ---------------------------------------------------------------------------
__global__ void __launch_bounds__(256) attn_vec_kernel(const float* __restrict__ a) {
    const int warp = threadIdx.x >> 5;
    const int lane = threadIdx.x & 31;
    const int r = blockIdx.x * 8 + warp;

    float2 v = ((const float2*)(g_WH + (size_t)r * OUT_F))[lane];
    float d1 = v.x * a[2 * lane] + v.y * a[2 * lane + 1];
    float d2 = v.x * a[OUT_F + 2 * lane] + v.y * a[OUT_F + 2 * lane + 1];
#pragma unroll
    for (int off = 16; off > 0; off >>= 1) {
        d1 += __shfl_xor_sync(0xFFFFFFFFu, d1, off);
        d2 += __shfl_xor_sync(0xFFFFFFFFu, d2, off);
    }
    if (lane == 0) {
        g_wh1[r] = d1;
        g_wh2[r] = d2;
    }
}

// ---------------------------------------------------------------------------
// Kernel B2: global softmax shift M = max(wh1) + max(wh2)
// ---------------------------------------------------------------------------
__global__ void __launch_bounds__(1024) max_kernel() {
    __shared__ float s1[1024], s2[1024];
    const int t = threadIdx.x;
    float m1 = -1e30f, m2 = -1e30f;
#pragma unroll
    for (int i = 0; i < N / 1024; i++) {
        m1 = fmaxf(m1, g_wh1[t + i * 1024]);
        m2 = fmaxf(m2, g_wh2[t + i * 1024]);
    }
    s1[t] = m1; s2[t] = m2;
    __syncthreads();
    for (int s = 512; s > 0; s >>= 1) {
        if (t < s) {
            s1[t] = fmaxf(s1[t], s1[t + s]);
            s2[t] = fmaxf(s2[t], s2[t + s]);
        }
        __syncthreads();
    }
    if (t == 0) g_M = s1[0] + s2[0];
}

// ---------------------------------------------------------------------------
// Kernel C: fused masked attention + partial PV matmul
//  grid (N/TI, SPLIT); each CTA covers rows [i0,i0+64) x cols [jbase,jbase+2048)
//  writes unnormalized partial acc + partial row-sums to global scratch.
// ---------------------------------------------------------------------------
__global__ void __launch_bounds__(256) gat_kernel(const int* __restrict__ adj) {
    __shared__ __align__(16) float VB[2 * TJ * OUT_F];  // 32 KB double-buffered V
    __shared__ __align__(16) float Ps[TI * PSTR];       // 17 KB
    __shared__ __align__(16) float wh2s[2][TJ];
    __shared__ float wh1s[TI];
    __shared__ float red[TI * 16];
    __shared__ float s_s[TI];

    const int t     = threadIdx.x;
    const int tx    = t & 15;            // matmul: feature group tx*4..tx*4+3
    const int ty    = t >> 4;            // matmul: rows ty*4..ty*4+3
    const int rsc   = t >> 4;            // score rows: rsc + 16k
    const int jb    = (t & 15) * 4;      // score cols within tile
    const int i0    = blockIdx.x * TI;
    const int sp    = blockIdx.y;
    const int jbase = sp * JSPAN;

    if (t < TI) wh1s[t] = g_wh1[i0 + t];
    const float Mv = g_M;

    // -- prologue: prefetch tile 0 --
#pragma unroll
    for (int i = 0; i < 4; i++) {
        int idx = t + i * 256;
        CP_ASYNC16(su(&VB[idx * 4]), (const void*)&g_WH[(size_t)jbase * OUT_F + idx * 4]);
    }
    if (t < 16) CP_ASYNC16(su(&wh2s[0][t * 4]), (const void*)&g_wh2[jbase + t * 4]);
    CP_COMMIT();

    int4 a4[4];
#pragma unroll
    for (int k = 0; k < 4; k++)
        a4[k] = *(const int4*)(adj + (size_t)(i0 + rsc + 16 * k) * N + jbase + jb);

    float sums[4] = {0.f, 0.f, 0.f, 0.f};
    unsigned long long acc[4][2];
#pragma unroll
    for (int i = 0; i < 4; i++) { acc[i][0] = 0ull; acc[i][1] = 0ull; }

    for (int it = 0; it < NT_S; ++it) {
        const int b = it & 1;
        CP_WAIT0();
        __syncthreads();   // V[it] visible; prev matmul done (Ps reusable)

        // ---- scores + exp + register row-sums ----
#pragma unroll
        for (int k = 0; k < 4; k++) {
            const int r = rsc + 16 * k;
            const float b1 = wh1s[r];
            const float4 w2 = *(const float4*)&wh2s[b][jb];
            float e0 = b1 + w2.x; e0 = (e0 > 0.f) ? e0 : NEG_SLOPE * e0;
            float e1 = b1 + w2.y; e1 = (e1 > 0.f) ? e1 : NEG_SLOPE * e1;
            float e2 = b1 + w2.z; e2 = (e2 > 0.f) ? e2 : NEG_SLOPE * e2;
            float e3 = b1 + w2.w; e3 = (e3 > 0.f) ? e3 : NEG_SLOPE * e3;
            float p0 = (a4[k].x > 0) ? __expf(e0 - Mv) : 0.f;
            float p1 = (a4[k].y > 0) ? __expf(e1 - Mv) : 0.f;
            float p2 = (a4[k].z > 0) ? __expf(e2 - Mv) : 0.f;
            float p3 = (a4[k].w > 0) ? __expf(e3 - Mv) : 0.f;
            sums[k] += (p0 + p1) + (p2 + p3);
            *(float4*)&Ps[r * PSTR + jb] = make_float4(p0, p1, p2, p3);
        }

        // ---- prefetch next tile ----
        if (it + 1 < NT_S) {
            const int jn = jbase + (it + 1) * TJ;
#pragma unroll
            for (int k = 0; k < 4; k++)
                a4[k] = *(const int4*)(adj + (size_t)(i0 + rsc + 16 * k) * N + jn + jb);
            float* vb = VB + (b ^ 1) * (TJ * OUT_F);
#pragma unroll
            for (int i = 0; i < 4; i++) {
                int idx = t + i * 256;
                CP_ASYNC16(su(&vb[idx * 4]), (const void*)&g_WH[(size_t)jn * OUT_F + idx * 4]);
            }
            if (t < 16) CP_ASYNC16(su(&wh2s[b ^ 1][t * 4]), (const void*)&g_wh2[jn + t * 4]);
        }
        CP_COMMIT();
        __syncthreads();   // Ps visible

        // ---- matmul: acc += P-tile @ V-tile  (packed f32x2) ----
        const float* vb = VB + b * (TJ * OUT_F);
#pragma unroll 4
        for (int j = 0; j < TJ; j += 2) {
            ulonglong2 w0 = *(const ulonglong2*)&vb[(j + 0) * OUT_F + tx * 4];
            ulonglong2 w1 = *(const ulonglong2*)&vb[(j + 1) * OUT_F + tx * 4];
#pragma unroll
            for (int i = 0; i < 4; i++) {
                float2 p = *(const float2*)&Ps[(ty * 4 + i) * PSTR + j];
                unsigned long long pxx, pyy;
                asm("mov.b64 %0, {%1, %1};" : "=l"(pxx) : "f"(p.x));
                asm("fma.rn.f32x2 %0, %1, %2, %0;" : "+l"(acc[i][0]) : "l"(pxx), "l"(w0.x));
                asm("fma.rn.f32x2 %0, %1, %2, %0;" : "+l"(acc[i][1]) : "l"(pxx), "l"(w0.y));
                asm("mov.b64 %0, {%1, %1};" : "=l"(pyy) : "f"(p.y));
                asm("fma.rn.f32x2 %0, %1, %2, %0;" : "+l"(acc[i][0]) : "l"(pyy), "l"(w1.x));
                asm("fma.rn.f32x2 %0, %1, %2, %0;" : "+l"(acc[i][1]) : "l"(pyy), "l"(w1.y));
            }
        }
    }

    // ---- row-sum reduction (16 partials per row) ----
#pragma unroll
    for (int k = 0; k < 4; k++)
        red[(rsc + 16 * k) * 16 + tx] = sums[k];
    __syncthreads();
    if (t < TI) {
        float s = 0.f;
#pragma unroll
        for (int q = 0; q < 16; q++) s += red[t * 16 + q];
        g_psum[sp * N + i0 + t] = s;
    }

    // ---- store unnormalized partials ----
#pragma unroll
    for (int i = 0; i < 4; i++) {
        const int r = ty * 4 + i;
        float v0, v1, v2, v3;
        asm("mov.b64 {%0, %1}, %2;" : "=f"(v0), "=f"(v1) : "l"(acc[i][0]));
        asm("mov.b64 {%0, %1}, %2;" : "=f"(v2), "=f"(v3) : "l"(acc[i][1]));
        ((float4*)g_pacc)[(size_t)sp * (N * 16) + (size_t)(i0 + r) * 16 + tx] =
            make_float4(v0, v1, v2, v3);
    }
    (void)s_s;
}

// ---------------------------------------------------------------------------
// Kernel D: combine partials, normalize, elu
// ---------------------------------------------------------------------------
__global__ void __launch_bounds__(256) combine_kernel(float* __restrict__ out) {
    const int idx = blockIdx.x * 256 + threadIdx.x;   // N*16 float4 slots
    const int r = idx >> 4;

    float4 a = make_float4(0.f, 0.f, 0.f, 0.f);
    float s = 0.f;
#pragma unroll
    for (int sp = 0; sp < SPLIT; sp++) {
        float4 p = ((const float4*)g_pacc)[(size_t)sp * (N * 16) + idx];
        a.x += p.x; a.y += p.y; a.z += p.z; a.w += p.w;
        s += g_psum[sp * N + r];
    }
    const float inv = 1.f / s;
    float v;
    float4 o;
    v = a.x * inv; o.x = (v > 0.f) ? v : expm1f(v);
    v = a.y * inv; o.y = (v > 0.f) ? v : expm1f(v);
    v = a.z * inv; o.z = (v > 0.f) ? v : expm1f(v);
    v = a.w * inv; o.w = (v > 0.f) ? v : expm1f(v);
    ((float4*)out)[idx] = o;
}

// ---------------------------------------------------------------------------
extern "C" void kernel_launch(void* const* d_in, const int* in_sizes, int n_in,
                              void* d_out, int out_size) {
    const float* h   = nullptr;
    const int*   adj = nullptr;
    const float* W   = nullptr;
    const float* a   = nullptr;
    for (int i = 0; i < n_in; i++) {
        long long sz = in_sizes[i];
        if (sz == (long long)N * IN_F)          h   = (const float*)d_in[i];
        else if (sz == (long long)N * N)        adj = (const int*)d_in[i];
        else if (sz == (long long)IN_F * OUT_F) W   = (const float*)d_in[i];
        else if (sz == 2 * OUT_F)               a   = (const float*)d_in[i];
    }

    wh_kernel<<<N / 16, 256>>>(h, W);
    attn_vec_kernel<<<N / 8, 256>>>(a);
    max_kernel<<<1, 1024>>>();
    gat_kernel<<<dim3(N / TI, SPLIT), 256>>>(adj);
    combine_kernel<<<(N * 16) / 256, 256>>>((float*)d_out);
}

// round 6
// speedup vs baseline: 3.7117x; 2.0551x over previous
#include <cuda_runtime.h>
#include <cstdint>

#define N 8192
#define IN_F 512
#define OUT_F 64
#define NEG_SLOPE 0.01f

#define TI 64
#define TJ 64
#define SPLIT 8
#define JSPAN (N / SPLIT)     // 1024
#define NT_S (JSPAN / TJ)     // 16

#define PSTR 68   // Ps row stride (words): banks (r*4+c)%32 conflict-free for frags
#define VSTR 72   // Vs row stride (words): banks (k*8+n)%32 conflict-free for frags

// Scratch (allocation-free rule: device globals)
__device__ __align__(16) float g_WH[N * OUT_F];
__device__ float g_wh1[N];
__device__ float g_wh2[N];
__device__ float g_M;
__device__ __align__(16) float g_pacc[SPLIT * N * OUT_F];   // 16 MB partial PV
__device__ float g_psum[SPLIT * N];                         // partial row sums

__device__ __forceinline__ uint32_t su(const void* p) {
    return (uint32_t)__cvta_generic_to_shared(p);
}
#define CP_ASYNC16(dst, src) \
    asm volatile("cp.async.cg.shared.global [%0], [%1], 16;" :: "r"(dst), "l"(src))
#define CP_COMMIT() asm volatile("cp.async.commit_group;" ::: "memory")
#define CP_WAIT0()  asm volatile("cp.async.wait_group 0;" ::: "memory")

// tf32 m16n8k8 tensor-core mma (baseline PTX, valid on sm_103 non-a target)
__device__ __forceinline__ void mma_tf32(float* c, uint32_t a0, uint32_t a1,
                                         uint32_t a2, uint32_t a3,
                                         uint32_t b0, uint32_t b1) {
    asm volatile(
        "mma.sync.aligned.m16n8k8.row.col.f32.tf32.tf32.f32 "
        "{%0,%1,%2,%3}, {%4,%5,%6,%7}, {%8,%9}, {%0,%1,%2,%3};"
        : "+f"(c[0]), "+f"(c[1]), "+f"(c[2]), "+f"(c[3])
        : "r"(a0), "r"(a1), "r"(a2), "r"(a3), "r"(b0), "r"(b1));
}

// ---------------------------------------------------------------------------
// Kernel A: WH = h @ W   [8192,512] @ [512,64]
// ---------------------------------------------------------------------------
__global__ void __launch_bounds__(256) wh_kernel(const float* __restrict__ h,
                                                 const float* __restrict__ W) {
    __shared__ __align__(16) float Wc[128 * OUT_F];  // 32 KB
    __shared__ __align__(16) float hc[16 * 128];     // 8 KB

    const int t  = threadIdx.x;
    const int f  = t & 63;
    const int rg = t >> 6;
    const int r0 = blockIdx.x * 16;

    float acc[4] = {0.f, 0.f, 0.f, 0.f};

    for (int kc = 0; kc < IN_F; kc += 128) {
        __syncthreads();
#pragma unroll
        for (int i = 0; i < 8; i++) {
            int idx = t + i * 256;
            ((float4*)Wc)[idx] = ((const float4*)W)[(size_t)(kc + (idx >> 4)) * 16 + (idx & 15)];
        }
#pragma unroll
        for (int i = 0; i < 2; i++) {
            int idx = t + i * 256;
            ((float4*)hc)[idx] =
                ((const float4*)h)[(size_t)(r0 + (idx >> 5)) * (IN_F / 4) + (kc >> 2) + (idx & 31)];
        }
        __syncthreads();
#pragma unroll 8
        for (int k = 0; k < 128; k++) {
            float w = Wc[k * 64 + f];
#pragma unroll
            for (int i = 0; i < 4; i++)
                acc[i] += hc[(rg * 4 + i) * 128 + k] * w;
        }
    }
#pragma unroll
    for (int i = 0; i < 4; i++)
        g_WH[(size_t)(r0 + rg * 4 + i) * OUT_F + f] = acc[i];
}

// ---------------------------------------------------------------------------
// Kernel B: wh1/wh2 row dots
// ---------------------------------------------------------------------------
__global__ void __launch_bounds__(256) attn_vec_kernel(const float* __restrict__ a) {
    const int warp = threadIdx.x >> 5;
    const int lane = threadIdx.x & 31;
    const int r = blockIdx.x * 8 + warp;

    float2 v = ((const float2*)(g_WH + (size_t)r * OUT_F))[lane];
    float d1 = v.x * a[2 * lane] + v.y * a[2 * lane + 1];
    float d2 = v.x * a[OUT_F + 2 * lane] + v.y * a[OUT_F + 2 * lane + 1];
#pragma unroll
    for (int off = 16; off > 0; off >>= 1) {
        d1 += __shfl_xor_sync(0xFFFFFFFFu, d1, off);
        d2 += __shfl_xor_sync(0xFFFFFFFFu, d2, off);
    }
    if (lane == 0) {
        g_wh1[r] = d1;
        g_wh2[r] = d2;
    }
}

// ---------------------------------------------------------------------------
// Kernel B2: global softmax shift M = max(wh1) + max(wh2)
// ---------------------------------------------------------------------------
__global__ void __launch_bounds__(1024) max_kernel() {
    __shared__ float s1[1024], s2[1024];
    const int t = threadIdx.x;
    float m1 = -1e30f, m2 = -1e30f;
#pragma unroll
    for (int i = 0; i < N / 1024; i++) {
        m1 = fmaxf(m1, g_wh1[t + i * 1024]);
        m2 = fmaxf(m2, g_wh2[t + i * 1024]);
    }
    s1[t] = m1; s2[t] = m2;
    __syncthreads();
    for (int s = 512; s > 0; s >>= 1) {
        if (t < s) {
            s1[t] = fmaxf(s1[t], s1[t + s]);
            s2[t] = fmaxf(s2[t], s2[t + s]);
        }
        __syncthreads();
    }
    if (t == 0) g_M = s1[0] + s2[0];
}

// ---------------------------------------------------------------------------
// Kernel C: scores (SIMT) -> PV matmul (tf32 mma.sync tensor cores)
//  grid (N/TI, SPLIT); partial results to scratch; combine kernel finishes.
//  Warp w owns output block rows [(w>>1)*16, +16) x cols [(w&1)*32, +32).
// ---------------------------------------------------------------------------
__global__ void __launch_bounds__(256, 3) gat_kernel(const int* __restrict__ adj) {
    __shared__ __align__(16) float Ps[TI * PSTR];       // 17.0 KB scores
    __shared__ __align__(16) float Vs[TJ * VSTR];       // 18.0 KB V tile
    __shared__ __align__(16) float wh2s[2][TJ];
    __shared__ float wh1s[TI];
    __shared__ float red[TI * 16];

    const int t    = threadIdx.x;
    const int ry   = t >> 4;            // score rows: ry + 16k
    const int jb   = (t & 15) * 4;      // score cols within tile
    const int lane = t & 31;
    const int warp = t >> 5;
    const int gid  = lane >> 2;         // mma group id (0..7)
    const int tid  = lane & 3;          // mma thread-in-group (0..3)
    const int rs   = (warp >> 1) * 16;  // mma row stripe
    const int ch   = (warp & 1) * 32;   // mma col half
    const int i0   = blockIdx.x * TI;
    const int sp   = blockIdx.y;
    const int jbase = sp * JSPAN;

    if (t < TI) wh1s[t] = g_wh1[i0 + t];
    if (t < 16) CP_ASYNC16(su(&wh2s[0][t * 4]), (const void*)(g_wh2 + jbase + t * 4));
    CP_COMMIT();

    int4 a4[4];
#pragma unroll
    for (int k = 0; k < 4; k++)
        a4[k] = *(const int4*)(adj + (size_t)(i0 + ry + 16 * k) * N + jbase + jb);

    const float Mv = g_M;
    float sums[4] = {0.f, 0.f, 0.f, 0.f};
    float c[4][4];
#pragma unroll
    for (int nt = 0; nt < 4; nt++)
#pragma unroll
        for (int q = 0; q < 4; q++) c[nt][q] = 0.f;

    CP_WAIT0();   // wh2s[0] resident (visibility via first in-loop sync)

    for (int tt = 0; tt < NT_S; ++tt) {
        const int b = tt & 1;
        const int j0 = jbase + tt * TJ;
        __syncthreads();   // mma(tt-1) done -> Ps/Vs free; wh2s[b] visible

        // ---- issue V tile (tt) + wh2 (tt+1) loads ----
#pragma unroll
        for (int i = 0; i < 4; i++) {
            int idx = t + i * 256;
            int row = idx >> 4, cc = idx & 15;
            CP_ASYNC16(su(Vs) + row * (VSTR * 4) + cc * 16,
                       (const void*)(g_WH + (size_t)(j0 + row) * OUT_F + cc * 4));
        }
        if (tt + 1 < NT_S && t < 16)
            CP_ASYNC16(su(&wh2s[b ^ 1][t * 4]), (const void*)(g_wh2 + j0 + TJ + t * 4));
        CP_COMMIT();

        // ---- scores -> Ps, register row sums, adjacency prefetch ----
        const float4 w2 = *(const float4*)&wh2s[b][jb];
#pragma unroll
        for (int k = 0; k < 4; k++) {
            const int r = ry + 16 * k;
            const float b1 = wh1s[r];
            float e0 = b1 + w2.x; e0 = (e0 > 0.f) ? e0 : NEG_SLOPE * e0;
            float e1 = b1 + w2.y; e1 = (e1 > 0.f) ? e1 : NEG_SLOPE * e1;
            float e2 = b1 + w2.z; e2 = (e2 > 0.f) ? e2 : NEG_SLOPE * e2;
            float e3 = b1 + w2.w; e3 = (e3 > 0.f) ? e3 : NEG_SLOPE * e3;
            float p0 = (a4[k].x > 0) ? __expf(e0 - Mv) : 0.f;
            float p1 = (a4[k].y > 0) ? __expf(e1 - Mv) : 0.f;
            float p2 = (a4[k].z > 0) ? __expf(e2 - Mv) : 0.f;
            float p3 = (a4[k].w > 0) ? __expf(e3 - Mv) : 0.f;
            sums[k] += (p0 + p1) + (p2 + p3);
            *(float4*)&Ps[r * PSTR + jb] = make_float4(p0, p1, p2, p3);
            if (tt + 1 < NT_S)
                a4[k] = *(const int4*)(adj + (size_t)(i0 + r) * N + j0 + TJ + jb);
        }

        CP_WAIT0();
        __syncthreads();   // Ps + Vs ready

        // ---- tensor-core PV: per warp 16x32 output, k=64 in chunks of 8 ----
#pragma unroll
        for (int k8 = 0; k8 < 8; k8++) {
            const int k0 = k8 * 8;
            uint32_t a0 = __float_as_uint(Ps[(rs + gid) * PSTR + k0 + tid]);
            uint32_t a1 = __float_as_uint(Ps[(rs + gid + 8) * PSTR + k0 + tid]);
            uint32_t a2 = __float_as_uint(Ps[(rs + gid) * PSTR + k0 + tid + 4]);
            uint32_t a3 = __float_as_uint(Ps[(rs + gid + 8) * PSTR + k0 + tid + 4]);
#pragma unroll
            for (int nt = 0; nt < 4; nt++) {
                uint32_t b0 = __float_as_uint(Vs[(k0 + tid) * VSTR + ch + nt * 8 + gid]);
                uint32_t b1 = __float_as_uint(Vs[(k0 + tid + 4) * VSTR + ch + nt * 8 + gid]);
                mma_tf32(c[nt], a0, a1, a2, a3, b0, b1);
            }
        }
    }

    // ---- row-sum reduction -> g_psum ----
#pragma unroll
    for (int k = 0; k < 4; k++)
        red[(ry + 16 * k) * 16 + (t & 15)] = sums[k];
    __syncthreads();
    if (t < TI) {
        float s = 0.f;
#pragma unroll
        for (int q = 0; q < 16; q++) s += red[t * 16 + q];
        g_psum[sp * N + i0 + t] = s;
    }

    // ---- store unnormalized partials from mma accumulators ----
#pragma unroll
    for (int nt = 0; nt < 4; nt++) {
        const int col = ch + nt * 8 + 2 * tid;
        const int row0 = i0 + rs + gid;
        *(float2*)&g_pacc[((size_t)sp * N + row0) * OUT_F + col] =
            make_float2(c[nt][0], c[nt][1]);
        *(float2*)&g_pacc[((size_t)sp * N + row0 + 8) * OUT_F + col] =
            make_float2(c[nt][2], c[nt][3]);
    }
}

// ---------------------------------------------------------------------------
// Kernel D: combine partials, normalize, elu
// ---------------------------------------------------------------------------
__global__ void __launch_bounds__(256) combine_kernel(float* __restrict__ out) {
    const int idx = blockIdx.x * 256 + threadIdx.x;   // N*16 float4 slots
    const int r = idx >> 4;

    float4 a = make_float4(0.f, 0.f, 0.f, 0.f);
    float s = 0.f;
#pragma unroll
    for (int sp = 0; sp < SPLIT; sp++) {
        float4 p = ((const float4*)g_pacc)[(size_t)sp * (N * 16) + idx];
        a.x += p.x; a.y += p.y; a.z += p.z; a.w += p.w;
        s += g_psum[sp * N + r];
    }
    const float inv = 1.f / s;
    float v;
    float4 o;
    v = a.x * inv; o.x = (v > 0.f) ? v : expm1f(v);
    v = a.y * inv; o.y = (v > 0.f) ? v : expm1f(v);
    v = a.z * inv; o.z = (v > 0.f) ? v : expm1f(v);
    v = a.w * inv; o.w = (v > 0.f) ? v : expm1f(v);
    ((float4*)out)[idx] = o;
}

// ---------------------------------------------------------------------------
extern "C" void kernel_launch(void* const* d_in, const int* in_sizes, int n_in,
                              void* d_out, int out_size) {
    const float* h   = nullptr;
    const int*   adj = nullptr;
    const float* W   = nullptr;
    const float* a   = nullptr;
    for (int i = 0; i < n_in; i++) {
        long long sz = in_sizes[i];
        if (sz == (long long)N * IN_F)          h   = (const float*)d_in[i];
        else if (sz == (long long)N * N)        adj = (const int*)d_in[i];
        else if (sz == (long long)IN_F * OUT_F) W   = (const float*)d_in[i];
        else if (sz == 2 * OUT_F)               a   = (const float*)d_in[i];
    }

    wh_kernel<<<N / 16, 256>>>(h, W);
    attn_vec_kernel<<<N / 8, 256>>>(a);
    max_kernel<<<1, 1024>>>();
    gat_kernel<<<dim3(N / TI, SPLIT), 256>>>(adj);
    combine_kernel<<<(N * 16) / 256, 256>>>((float*)d_out);
}